// round 1
// baseline (speedup 1.0000x reference)
#include <cuda_runtime.h>
#include <cuda_bf16.h>

#define BATCH 64
#define CHANS 3
#define HH 384
#define WW 384
#define HW (HH * WW)

__global__ __launch_bounds__(256)
void affine_kernel(const float* __restrict__ imgs,
                   const float* __restrict__ theta,
                   float* __restrict__ out) {
    const int pix = blockIdx.x * blockDim.x + threadIdx.x;
    if (pix >= HW) return;
    const int b = blockIdx.y;
    const int row = pix / WW;
    const int col = pix - row * WW;

    // theta for this batch (uniform per block -> L1 broadcast)
    const float* th = theta + b * 6;
    const float t00 = __ldg(th + 0);
    const float t01 = __ldg(th + 1);
    const float t02 = __ldg(th + 2);
    const float t10 = __ldg(th + 3);
    const float t11 = __ldg(th + 4);
    const float t12 = __ldg(th + 5);

    // Collapsed grid math:
    //   xs[col] = col - 191.5, ys[row] = row - 191.5
    //   ix = t00*xs + t01*ys + t02 + 191.5
    //   iy = t10*xs + t11*ys + t12 + 191.5
    const float xc = (float)col - 191.5f;
    const float yc = (float)row - 191.5f;
    const float ix = fmaf(t00, xc, fmaf(t01, yc, t02)) + 191.5f;
    const float iy = fmaf(t10, xc, fmaf(t11, yc, t12)) + 191.5f;

    const float x0f = floorf(ix);
    const float y0f = floorf(iy);
    const float wx1 = ix - x0f;
    const float wy1 = iy - y0f;
    const float wx0 = 1.0f - wx1;
    const float wy0 = 1.0f - wy1;

    const int x0 = (int)x0f;
    const int y0 = (int)y0f;
    const int x1 = x0 + 1;
    const int y1 = y0 + 1;

    // validity folded into weights (identical to ref's value*mask for finite data)
    const float vx0 = (x0 >= 0 && x0 < WW) ? 1.0f : 0.0f;
    const float vx1 = (x1 >= 0 && x1 < WW) ? 1.0f : 0.0f;
    const float vy0 = (y0 >= 0 && y0 < HH) ? 1.0f : 0.0f;
    const float vy1 = (y1 >= 0 && y1 < HH) ? 1.0f : 0.0f;

    const float w00 = wx0 * wy0 * vx0 * vy0;
    const float w10 = wx1 * wy0 * vx1 * vy0;
    const float w01 = wx0 * wy1 * vx0 * vy1;
    const float w11 = wx1 * wy1 * vx1 * vy1;

    const int x0c = min(max(x0, 0), WW - 1);
    const int x1c = min(max(x1, 0), WW - 1);
    const int y0c = min(max(y0, 0), HH - 1);
    const int y1c = min(max(y1, 0), HH - 1);

    const int o00 = y0c * WW + x0c;
    const int o10 = y0c * WW + x1c;
    const int o01 = y1c * WW + x0c;
    const int o11 = y1c * WW + x1c;

    const float* img = imgs + (size_t)b * CHANS * HW;

    // Issue all 12 gathers up front (MLP), then reduce.
    float v00[CHANS], v10[CHANS], v01[CHANS], v11[CHANS];
#pragma unroll
    for (int c = 0; c < CHANS; c++) {
        const float* p = img + c * HW;
        v00[c] = __ldg(p + o00);
        v10[c] = __ldg(p + o10);
        v01[c] = __ldg(p + o01);
        v11[c] = __ldg(p + o11);
    }

    float* op = out + (size_t)b * CHANS * HW + pix;
#pragma unroll
    for (int c = 0; c < CHANS; c++) {
        float acc = v00[c] * w00;
        acc = fmaf(v10[c], w10, acc);
        acc = fmaf(v01[c], w01, acc);
        acc = fmaf(v11[c], w11, acc);
        op[c * HW] = acc;
    }
}

extern "C" void kernel_launch(void* const* d_in, const int* in_sizes, int n_in,
                              void* d_out, int out_size) {
    const float* imgs  = (const float*)d_in[0];
    const float* theta = (const float*)d_in[1];
    float* out = (float*)d_out;

    dim3 block(256);
    dim3 grid((HW + 255) / 256, BATCH);  // 576 x 64
    affine_kernel<<<grid, block>>>(imgs, theta, out);
}